// round 9
// baseline (speedup 1.0000x reference)
#include <cuda_runtime.h>
#include <cstdint>

#define VOCAB 50000
#define EDIM  256
#define HDIM  256
#define BATCH 64
#define TLEN  2048

typedef unsigned long long u64;

// proj_table[v][h] = sum_e emb[v][e] * W_ih[h][e]   (51.2 MB device scratch)
__device__ float g_proj[VOCAB * HDIM];

// ---------------------------------------------------------------------------
// Kernel A: proj = emb @ W_ih^T   (NT SGEMM, C[50000,256])  -- unchanged
// ---------------------------------------------------------------------------
__global__ __launch_bounds__(256) void proj_kernel(const float* __restrict__ emb,
                                                   const float* __restrict__ Wih) {
    __shared__ float As[32][128];
    __shared__ float Bs[32][128];

    const int n0 = blockIdx.x * 128;
    const int m0 = blockIdx.y * 128;
    const int tid = threadIdx.x;
    const int tx = tid & 15;
    const int ty = tid >> 4;

    float acc[8][8];
#pragma unroll
    for (int a = 0; a < 8; a++)
#pragma unroll
        for (int bb = 0; bb < 8; bb++) acc[a][bb] = 0.0f;

    for (int kc = 0; kc < EDIM; kc += 32) {
#pragma unroll
        for (int q = 0; q < 4; q++) {
            int fid = tid + 256 * q;
            int row = fid >> 3;
            int col = fid & 7;
            float4 av = make_float4(0.f, 0.f, 0.f, 0.f);
            int m = m0 + row;
            if (m < VOCAB)
                av = __ldg((const float4*)(emb + (size_t)m * EDIM + kc + col * 4));
            As[col * 4 + 0][row] = av.x;
            As[col * 4 + 1][row] = av.y;
            As[col * 4 + 2][row] = av.z;
            As[col * 4 + 3][row] = av.w;
            float4 bv = __ldg((const float4*)(Wih + (size_t)(n0 + row) * EDIM + kc + col * 4));
            Bs[col * 4 + 0][row] = bv.x;
            Bs[col * 4 + 1][row] = bv.y;
            Bs[col * 4 + 2][row] = bv.z;
            Bs[col * 4 + 3][row] = bv.w;
        }
        __syncthreads();

#pragma unroll
        for (int k = 0; k < 32; k++) {
            float a[8], b[8];
            *(float4*)&a[0] = *(const float4*)&As[k][ty * 8];
            *(float4*)&a[4] = *(const float4*)&As[k][ty * 8 + 4];
            *(float4*)&b[0] = *(const float4*)&Bs[k][tx * 8];
            *(float4*)&b[4] = *(const float4*)&Bs[k][tx * 8 + 4];
#pragma unroll
            for (int ii = 0; ii < 8; ii++)
#pragma unroll
                for (int jj = 0; jj < 8; jj++) acc[ii][jj] += a[ii] * b[jj];
        }
        __syncthreads();
    }

#pragma unroll
    for (int ii = 0; ii < 8; ii++) {
        int m = m0 + ty * 8 + ii;
        if (m < VOCAB) {
            float4 v0 = make_float4(acc[ii][0], acc[ii][1], acc[ii][2], acc[ii][3]);
            float4 v1 = make_float4(acc[ii][4], acc[ii][5], acc[ii][6], acc[ii][7]);
            *(float4*)(g_proj + (size_t)m * HDIM + n0 + tx * 8)     = v0;
            *(float4*)(g_proj + (size_t)m * HDIM + n0 + tx * 8 + 4) = v1;
        }
    }
}

// ---------------------------------------------------------------------------
// Kernel B: RNN scan, TWO batches per cluster, interleaved so each batch's
// cross-SM h-exchange latency hides under the OTHER batch's compute.
// 32 clusters x 2 CTAs x 1024 threads. Exchange = st.async.v4 (16B/warp,
// data + complete_tx) into peer smem; one expect_tx(512) per barrier per
// step; waits hit the mbarrier fast path (data arrived a full batch-compute
// earlier). W_hh registers are SHARED between the two batches.
// ---------------------------------------------------------------------------
__device__ __forceinline__ void fma2(u64& acc, u64 a, u64 b) {
    asm("fma.rn.f32x2 %0, %1, %2, %0;" : "+l"(acc) : "l"(a), "l"(b));
}
__device__ __forceinline__ uint32_t s2u(const void* p) {
    return (uint32_t)__cvta_generic_to_shared(p);
}
__device__ __forceinline__ uint32_t mapa_u32(uint32_t a, uint32_t r) {
    uint32_t ret;
    asm("mapa.shared::cluster.u32 %0, %1, %2;" : "=r"(ret) : "r"(a), "r"(r));
    return ret;
}
__device__ __forceinline__ void st_remote_f32(uint32_t ra, float v) {
    asm volatile("st.shared::cluster.f32 [%0], %1;" :: "r"(ra), "f"(v) : "memory");
}
__device__ __forceinline__ void mbar_init(uint32_t a, uint32_t cnt) {
    asm volatile("mbarrier.init.shared.b64 [%0], %1;" :: "r"(a), "r"(cnt) : "memory");
}
__device__ __forceinline__ void mbar_expect_tx(uint32_t a, uint32_t bytes) {
    asm volatile("mbarrier.arrive.expect_tx.shared.b64 _, [%0], %1;"
                 :: "r"(a), "r"(bytes) : "memory");
}
__device__ __forceinline__ void st_async_v4(uint32_t raddr, float x, float y,
                                            float z, float w, uint32_t rmbar) {
    asm volatile(
        "st.async.shared::cluster.mbarrier::complete_tx::bytes.v4.f32 "
        "[%0], {%1, %2, %3, %4}, [%5];"
        :: "r"(raddr), "f"(x), "f"(y), "f"(z), "f"(w), "r"(rmbar) : "memory");
}
__device__ __forceinline__ void mbar_wait_acq(uint32_t a, uint32_t par) {
    asm volatile(
        "{\n\t.reg .pred P;\n"
        "LW%=:\n\t"
        "mbarrier.try_wait.parity.acquire.cluster.shared::cta.b64 P, [%0], %1, 0x989680;\n\t"
        "@!P bra LW%=;\n\t}"
        :: "r"(a), "r"(par) : "memory");
}
__device__ __forceinline__ void cl_arrive() {
    asm volatile("barrier.cluster.arrive.aligned;" ::: "memory");
}
__device__ __forceinline__ void cl_wait() {
    asm volatile("barrier.cluster.wait.aligned;" ::: "memory");
}
// exact-enough tanh (validated rel_err ~2.7e-7 end-to-end, R5-R8)
__device__ __forceinline__ float fast_tanh(float x) {
    float xc = fminf(fmaxf(x, -15.0f), 15.0f);
    float e  = __expf(2.0f * xc);
    return __fdividef(e - 1.0f, e + 1.0f);
}
// phase parity for the wait at step t on barrier index (t&1); valid for t>=1
__device__ __forceinline__ uint32_t wait_par(int t) {
    return (uint32_t)(((t - 2 + (t & 1)) >> 1) & 1);
}

__global__ void __cluster_dims__(2, 1, 1) __launch_bounds__(1024, 1)
scan2_kernel(const int* __restrict__ reviews, const int* __restrict__ lengths,
             const float* __restrict__ Whh, const float* __restrict__ Wcls,
             const float* __restrict__ bcls, float* __restrict__ out) {
    __shared__ __align__(16) float hA[2][HDIM];
    __shared__ __align__(16) float hB[2][HDIM];
    __shared__ __align__(16) float hfA[HDIM];
    __shared__ __align__(16) float hfB[HDIM];
    __shared__ __align__(8) u64 mbA[2], mbB[2];
    __shared__ int toksA[TLEN], toksB[TLEN];

    const int tid  = threadIdx.x;
    const int w    = tid >> 5;              // 32 warps
    const int l    = tid & 31;
    const int g    = l & 7;                 // K-slice within output group
    const int i    = w * 4 + (l >> 3);      // local output index 0..127
    const int cp   = blockIdx.x >> 1;       // cluster id 0..31
    const int rank = blockIdx.x & 1;
    const int peer = rank ^ 1;
    const int bA   = cp * 2, bB = cp * 2 + 1;
    const int lenA = lengths[bA];
    const int lenB = lengths[bB];
    const int tmax = (lenA > lenB) ? lenA : lenB;
    const int ownK  = rank * 128;           // h range produced locally
    const int peerK = 128 - ownK;

    for (int idx = tid; idx < TLEN; idx += 1024) {
        toksA[idx] = reviews[bA * TLEN + idx];
        toksB[idx] = reviews[bB * TLEN + idx];
    }
    if (tid < HDIM) { hA[0][tid] = 0.0f; hB[0][tid] = 0.0f; }
    if (tid == 0) {
        mbar_init(s2u(&mbA[0]), 1); mbar_init(s2u(&mbA[1]), 1);
        mbar_init(s2u(&mbB[0]), 1); mbar_init(s2u(&mbB[1]), 1);
    }
    __syncthreads();
    cl_arrive(); cl_wait();                 // peer init visible

    // W_hh[ownK+i][.] split own-half / peer-half K (shared by both batches)
    u64 wOwn[8], wPeer[8];
    {
        const float* wr = Whh + (size_t)(ownK + i) * HDIM;
#pragma unroll
        for (int q = 0; q < 4; q++) {
            ulonglong2 a = *(const ulonglong2*)(wr + ownK + q * 32 + g * 4);
            wOwn[2 * q]     = a.x;
            wOwn[2 * q + 1] = a.y;
            ulonglong2 c = *(const ulonglong2*)(wr + peerK + q * 32 + g * 4);
            wPeer[2 * q]     = c.x;
            wPeer[2 * q + 1] = c.y;
        }
    }

    const int ow = ownK + i;
    const uint32_t mbA0 = s2u(&mbA[0]), mbA1 = s2u(&mbA[1]);
    const uint32_t mbB0 = s2u(&mbB[0]), mbB1 = s2u(&mbB[1]);
    // peer-side addresses for this warp's float4 slot (phase 0); phase 1 = +HDIM floats
    const uint32_t rDA0 = mapa_u32(s2u(&hA[0][ownK + w * 4]), peer);
    const uint32_t rDB0 = mapa_u32(s2u(&hB[0][ownK + w * 4]), peer);
    const uint32_t rBA0 = mapa_u32(mbA0, peer);
    const uint32_t rBB0 = mapa_u32(mbB0, peer);

    float xpA = __ldg(g_proj + (size_t)toksA[0] * HDIM + ow);
    float xpB = __ldg(g_proj + (size_t)toksB[0] * HDIM + ow);

    for (int t = 0; t < tmax; ++t) {
        const int p = t & 1, pn = p ^ 1;
        if (tid == 0) {
            mbar_expect_tx(pn ? mbA1 : mbA0, 512);
            mbar_expect_tx(pn ? mbB1 : mbB0, 512);
        }
        int tn = (t + 1 < TLEN) ? (t + 1) : (TLEN - 1);
        float xpA_next = __ldg(g_proj + (size_t)toksA[tn] * HDIM + ow);
        float xpB_next = __ldg(g_proj + (size_t)toksB[tn] * HDIM + ow);

        // ================= batch A =================
        {
            const float* hb = hA[p];
            u64 a0 = 0ull, a1 = 0ull, a2 = 0ull, a3 = 0ull;
#pragma unroll
            for (int q = 0; q < 4; q++) {
                ulonglong2 hh = *(const ulonglong2*)(hb + ownK + q * 32 + g * 4);
                fma2((q & 1) ? a1 : a0, wOwn[2 * q],     hh.x);
                fma2((q & 1) ? a3 : a2, wOwn[2 * q + 1], hh.y);
            }
            if (t > 0) mbar_wait_acq(p ? mbA1 : mbA0, wait_par(t));  // fast path
#pragma unroll
            for (int q = 0; q < 4; q++) {
                ulonglong2 hh = *(const ulonglong2*)(hb + peerK + q * 32 + g * 4);
                fma2((q & 1) ? a1 : a0, wPeer[2 * q],     hh.x);
                fma2((q & 1) ? a3 : a2, wPeer[2 * q + 1], hh.y);
            }
            float2 f0 = *(float2*)&a0, f1 = *(float2*)&a1;
            float2 f2 = *(float2*)&a2, f3 = *(float2*)&a3;
            float sum = (f0.x + f0.y) + (f1.x + f1.y) + (f2.x + f2.y) + (f3.x + f3.y);
            sum += __shfl_xor_sync(0xffffffffu, sum, 1);
            sum += __shfl_xor_sync(0xffffffffu, sum, 2);
            sum += __shfl_xor_sync(0xffffffffu, sum, 4);
            float v = fast_tanh(sum + xpA);
            xpA = xpA_next;
            float v1 = __shfl_sync(0xffffffffu, v, 8);
            float v2 = __shfl_sync(0xffffffffu, v, 16);
            float v3 = __shfl_sync(0xffffffffu, v, 24);
            if (l == 0) {
                *(float4*)&hA[pn][ownK + w * 4] = make_float4(v, v1, v2, v3);
                st_async_v4(rDA0 + (uint32_t)(pn * HDIM * 4), v, v1, v2, v3,
                            rBA0 + (uint32_t)(pn * 8));
                if (t == lenA - 1) {
                    *(float4*)&hfA[ownK + w * 4] = make_float4(v, v1, v2, v3);
                    uint32_t rf = mapa_u32(s2u(&hfA[ownK + w * 4]), peer);
                    st_remote_f32(rf,      v);
                    st_remote_f32(rf + 4,  v1);
                    st_remote_f32(rf + 8,  v2);
                    st_remote_f32(rf + 12, v3);
                }
            }
        }
        // ================= batch B =================
        {
            const float* hb = hB[p];
            u64 a0 = 0ull, a1 = 0ull, a2 = 0ull, a3 = 0ull;
#pragma unroll
            for (int q = 0; q < 4; q++) {
                ulonglong2 hh = *(const ulonglong2*)(hb + ownK + q * 32 + g * 4);
                fma2((q & 1) ? a1 : a0, wOwn[2 * q],     hh.x);
                fma2((q & 1) ? a3 : a2, wOwn[2 * q + 1], hh.y);
            }
            if (t > 0) mbar_wait_acq(p ? mbB1 : mbB0, wait_par(t));  // fast path
#pragma unroll
            for (int q = 0; q < 4; q++) {
                ulonglong2 hh = *(const ulonglong2*)(hb + peerK + q * 32 + g * 4);
                fma2((q & 1) ? a1 : a0, wPeer[2 * q],     hh.x);
                fma2((q & 1) ? a3 : a2, wPeer[2 * q + 1], hh.y);
            }
            float2 f0 = *(float2*)&a0, f1 = *(float2*)&a1;
            float2 f2 = *(float2*)&a2, f3 = *(float2*)&a3;
            float sum = (f0.x + f0.y) + (f1.x + f1.y) + (f2.x + f2.y) + (f3.x + f3.y);
            sum += __shfl_xor_sync(0xffffffffu, sum, 1);
            sum += __shfl_xor_sync(0xffffffffu, sum, 2);
            sum += __shfl_xor_sync(0xffffffffu, sum, 4);
            float v = fast_tanh(sum + xpB);
            xpB = xpB_next;
            float v1 = __shfl_sync(0xffffffffu, v, 8);
            float v2 = __shfl_sync(0xffffffffu, v, 16);
            float v3 = __shfl_sync(0xffffffffu, v, 24);
            if (l == 0) {
                *(float4*)&hB[pn][ownK + w * 4] = make_float4(v, v1, v2, v3);
                st_async_v4(rDB0 + (uint32_t)(pn * HDIM * 4), v, v1, v2, v3,
                            rBB0 + (uint32_t)(pn * 8));
                if (t == lenB - 1) {
                    *(float4*)&hfB[ownK + w * 4] = make_float4(v, v1, v2, v3);
                    uint32_t rf = mapa_u32(s2u(&hfB[ownK + w * 4]), peer);
                    st_remote_f32(rf,      v);
                    st_remote_f32(rf + 4,  v1);
                    st_remote_f32(rf + 8,  v2);
                    st_remote_f32(rf + 12, v3);
                }
            }
        }
        __syncthreads();                    // local halves visible CTA-wide
    }

    // all cross-CTA traffic (incl. hf stores) visible after full cluster sync
    cl_arrive(); cl_wait();

    if (rank == 0 && tid < 128) {
        const bool isA = (tid < 64);
        const int  c    = (tid >> 5) & 1;
        const int  lane = tid & 31;
        const float* hf = isA ? hfA : hfB;
        const int  bo   = isA ? bA : bB;
        float sum = 0.0f;
#pragma unroll
        for (int m = 0; m < 8; m++)
            sum += Wcls[c * HDIM + lane + 32 * m] * hf[lane + 32 * m];
#pragma unroll
        for (int o = 16; o > 0; o >>= 1) sum += __shfl_down_sync(0xffffffffu, sum, o);
        if (lane == 0) out[bo * 2 + c] = sum + bcls[c];
    }

    cl_arrive(); cl_wait();                 // keep CTAs alive for stragglers
}

// ---------------------------------------------------------------------------
extern "C" void kernel_launch(void* const* d_in, const int* in_sizes, int n_in,
                              void* d_out, int out_size) {
    const int*   reviews = (const int*)d_in[0];
    const int*   lengths = (const int*)d_in[1];
    const float* emb     = (const float*)d_in[2];
    const float* Wih     = (const float*)d_in[3];
    const float* Whh     = (const float*)d_in[4];
    const float* Wcls    = (const float*)d_in[5];
    const float* bcls    = (const float*)d_in[6];
    float*       out     = (float*)d_out;

    dim3 gA(2, (VOCAB + 127) / 128);
    proj_kernel<<<gA, 256>>>(emb, Wih);

    scan2_kernel<<<BATCH, 1024>>>(reviews, lengths, Whh, Wcls, bcls, out);
}

// round 10
// speedup vs baseline: 1.6091x; 1.6091x over previous
#include <cuda_runtime.h>
#include <cstdint>

#define VOCAB 50000
#define EDIM  256
#define HDIM  256
#define BATCH 64
#define TLEN  2048

#define CANARY 0x7FC00BADu

typedef unsigned long long u64;

// proj_table[v][h] = sum_e emb[v][e] * W_ih[h][e]   (51.2 MB device scratch)
__device__ float g_proj[VOCAB * HDIM];

// ---------------------------------------------------------------------------
// Kernel A: proj = emb @ W_ih^T   (NT SGEMM, C[50000,256])  -- unchanged
// ---------------------------------------------------------------------------
__global__ __launch_bounds__(256) void proj_kernel(const float* __restrict__ emb,
                                                   const float* __restrict__ Wih) {
    __shared__ float As[32][128];
    __shared__ float Bs[32][128];

    const int n0 = blockIdx.x * 128;
    const int m0 = blockIdx.y * 128;
    const int tid = threadIdx.x;
    const int tx = tid & 15;
    const int ty = tid >> 4;

    float acc[8][8];
#pragma unroll
    for (int a = 0; a < 8; a++)
#pragma unroll
        for (int bb = 0; bb < 8; bb++) acc[a][bb] = 0.0f;

    for (int kc = 0; kc < EDIM; kc += 32) {
#pragma unroll
        for (int q = 0; q < 4; q++) {
            int fid = tid + 256 * q;
            int row = fid >> 3;
            int col = fid & 7;
            float4 av = make_float4(0.f, 0.f, 0.f, 0.f);
            int m = m0 + row;
            if (m < VOCAB)
                av = __ldg((const float4*)(emb + (size_t)m * EDIM + kc + col * 4));
            As[col * 4 + 0][row] = av.x;
            As[col * 4 + 1][row] = av.y;
            As[col * 4 + 2][row] = av.z;
            As[col * 4 + 3][row] = av.w;
            float4 bv = __ldg((const float4*)(Wih + (size_t)(n0 + row) * EDIM + kc + col * 4));
            Bs[col * 4 + 0][row] = bv.x;
            Bs[col * 4 + 1][row] = bv.y;
            Bs[col * 4 + 2][row] = bv.z;
            Bs[col * 4 + 3][row] = bv.w;
        }
        __syncthreads();

#pragma unroll
        for (int k = 0; k < 32; k++) {
            float a[8], b[8];
            *(float4*)&a[0] = *(const float4*)&As[k][ty * 8];
            *(float4*)&a[4] = *(const float4*)&As[k][ty * 8 + 4];
            *(float4*)&b[0] = *(const float4*)&Bs[k][tx * 8];
            *(float4*)&b[4] = *(const float4*)&Bs[k][tx * 8 + 4];
#pragma unroll
            for (int ii = 0; ii < 8; ii++)
#pragma unroll
                for (int jj = 0; jj < 8; jj++) acc[ii][jj] += a[ii] * b[jj];
        }
        __syncthreads();
    }

#pragma unroll
    for (int ii = 0; ii < 8; ii++) {
        int m = m0 + ty * 8 + ii;
        if (m < VOCAB) {
            float4 v0 = make_float4(acc[ii][0], acc[ii][1], acc[ii][2], acc[ii][3]);
            float4 v1 = make_float4(acc[ii][4], acc[ii][5], acc[ii][6], acc[ii][7]);
            *(float4*)(g_proj + (size_t)m * HDIM + n0 + tx * 8)     = v0;
            *(float4*)(g_proj + (size_t)m * HDIM + n0 + tx * 8 + 4) = v1;
        }
    }
}

// ---------------------------------------------------------------------------
// Kernel B: RNN scan. 64 clusters x 2 CTAs x 1024 threads.
// NO sync primitive on the cross-CTA path: peer h arrives as 16B
// st.shared::cluster.v4 over a CANARY-poisoned double buffer; consumers
// spin on plain volatile local LDS until their 16 inputs are canary-free
// (the same loads feed the FMAs). Slots are re-poisoned one full round-trip
// before the peer can rewrite them (ordered by the step-ending
// __syncthreads). Zero-init != canary, so t=0 needs no special case.
// ---------------------------------------------------------------------------
__device__ __forceinline__ void fma2(u64& acc, u64 a, u64 b) {
    asm("fma.rn.f32x2 %0, %1, %2, %0;" : "+l"(acc) : "l"(a), "l"(b));
}
__device__ __forceinline__ u64 pk(uint32_t lo, uint32_t hi) {
    u64 r;
    asm("mov.b64 %0, {%1, %2};" : "=l"(r) : "r"(lo), "r"(hi));
    return r;
}
__device__ __forceinline__ uint32_t s2u(const void* p) {
    return (uint32_t)__cvta_generic_to_shared(p);
}
__device__ __forceinline__ uint32_t mapa_u32(uint32_t a, uint32_t r) {
    uint32_t ret;
    asm("mapa.shared::cluster.u32 %0, %1, %2;" : "=r"(ret) : "r"(a), "r"(r));
    return ret;
}
__device__ __forceinline__ void st_remote_v4(uint32_t ra, float x, float y,
                                             float z, float w) {
    asm volatile("st.shared::cluster.v4.f32 [%0], {%1, %2, %3, %4};"
                 :: "r"(ra), "f"(x), "f"(y), "f"(z), "f"(w) : "memory");
}
__device__ __forceinline__ uint4 ldsv4(uint32_t a) {
    uint4 r;
    asm volatile("ld.volatile.shared.v4.u32 {%0, %1, %2, %3}, [%4];"
                 : "=r"(r.x), "=r"(r.y), "=r"(r.z), "=r"(r.w) : "r"(a));
    return r;
}
__device__ __forceinline__ bool chk(uint4 c) {
    return (c.x != CANARY) & (c.y != CANARY) & (c.z != CANARY) & (c.w != CANARY);
}
__device__ __forceinline__ void cl_arrive() {
    asm volatile("barrier.cluster.arrive.aligned;" ::: "memory");
}
__device__ __forceinline__ void cl_wait() {
    asm volatile("barrier.cluster.wait.aligned;" ::: "memory");
}
// exact-enough tanh (validated rel_err ~2.7e-7 end-to-end, R5-R8)
__device__ __forceinline__ float fast_tanh(float x) {
    float xc = fminf(fmaxf(x, -15.0f), 15.0f);
    float e  = __expf(2.0f * xc);
    return __fdividef(e - 1.0f, e + 1.0f);
}

__global__ void __cluster_dims__(2, 1, 1) __launch_bounds__(1024, 1)
scan_kernel(const int* __restrict__ reviews, const int* __restrict__ lengths,
            const float* __restrict__ Whh, const float* __restrict__ Wcls,
            const float* __restrict__ bcls, float* __restrict__ out) {
    __shared__ __align__(16) float hbuf[2][HDIM];   // full h, double-buffered
    __shared__ int toks[TLEN];

    const int tid  = threadIdx.x;
    const int w    = tid >> 5;              // 32 warps
    const int l    = tid & 31;
    const int g    = l & 7;                 // K-slice within output group
    const int i    = w * 4 + (l >> 3);      // local output index 0..127
    const int b    = blockIdx.x >> 1;
    const int rank = blockIdx.x & 1;
    const int peer = rank ^ 1;
    const int len  = lengths[b];
    const int ownK  = rank * 128;           // h range produced locally
    const int peerK = 128 - ownK;

    for (int idx = tid; idx < TLEN; idx += 1024)
        toks[idx] = reviews[b * TLEN + idx];
    if (tid < HDIM) hbuf[0][tid] = 0.0f;                      // t=0 state
    if (tid < 128)  hbuf[1][peerK + tid] = __uint_as_float(CANARY);  // armed

    // W_hh[ownK+i][.] split own-half / peer-half K, packed f32x2
    u64 wOwn[8], wPeer[8];
    {
        const float* wr = Whh + (size_t)(ownK + i) * HDIM;
#pragma unroll
        for (int q = 0; q < 4; q++) {
            ulonglong2 a = *(const ulonglong2*)(wr + ownK + q * 32 + g * 4);
            wOwn[2 * q]     = a.x;
            wOwn[2 * q + 1] = a.y;
            ulonglong2 c = *(const ulonglong2*)(wr + peerK + q * 32 + g * 4);
            wPeer[2 * q]     = c.x;
            wPeer[2 * q + 1] = c.y;
        }
    }
    __syncthreads();
    cl_arrive(); cl_wait();                 // peer's canary init visible

    const int ow = ownK + i;
    // peer-side address of this warp's float4 output slot, phase 0
    const uint32_t rD0 = mapa_u32(s2u(&hbuf[0][ownK + w * 4]), peer);
    // local poll addresses: 4 x 16B chunks of the peer half this lane consumes
    uint32_t pa[2][4];
#pragma unroll
    for (int q = 0; q < 4; q++) {
        pa[0][q] = s2u(&hbuf[0][peerK + q * 32 + g * 4]);
        pa[1][q] = s2u(&hbuf[1][peerK + q * 32 + g * 4]);
    }

    float xp_cur = 0.0f;
    if (g == 0) xp_cur = __ldg(g_proj + (size_t)toks[0] * HDIM + ow);

    for (int t = 0; t < len; ++t) {
        const int p = t & 1, pn = p ^ 1;

        // prefetch next xp (only the g==0 lane adds it pre-reduce)
        float xp_next = 0.0f;
        if (g == 0) {
            int tn = (t + 1 < len) ? (t + 1) : t;
            xp_next = __ldg(g_proj + (size_t)toks[tn] * HDIM + ow);
        }

        const float* hb = hbuf[p];
        u64 a0 = 0ull, a1 = 0ull, a2 = 0ull, a3 = 0ull;
        // own-half K: locally produced, guarded by prior __syncthreads
#pragma unroll
        for (int q = 0; q < 4; q++) {
            ulonglong2 hh = *(const ulonglong2*)(hb + ownK + q * 32 + g * 4);
            fma2((q & 1) ? a1 : a0, wOwn[2 * q],     hh.x);
            fma2((q & 1) ? a3 : a2, wOwn[2 * q + 1], hh.y);
        }
        // poll peer half: loads double as FMA inputs once canary-free
        uint4 c0, c1, c2, c3;
        for (;;) {
            c0 = ldsv4(pa[p][0]);
            c1 = ldsv4(pa[p][1]);
            c2 = ldsv4(pa[p][2]);
            c3 = ldsv4(pa[p][3]);
            if (chk(c0) & chk(c1) & chk(c2) & chk(c3)) break;
        }
        fma2(a0, wPeer[0], pk(c0.x, c0.y));
        fma2(a2, wPeer[1], pk(c0.z, c0.w));
        fma2(a1, wPeer[2], pk(c1.x, c1.y));
        fma2(a3, wPeer[3], pk(c1.z, c1.w));
        fma2(a0, wPeer[4], pk(c2.x, c2.y));
        fma2(a2, wPeer[5], pk(c2.z, c2.w));
        fma2(a1, wPeer[6], pk(c3.x, c3.y));
        fma2(a3, wPeer[7], pk(c3.z, c3.w));

        float2 f0 = *(float2*)&a0, f1 = *(float2*)&a1;
        float2 f2 = *(float2*)&a2, f3 = *(float2*)&a3;
        float sum = (f0.x + f0.y) + (f1.x + f1.y) + (f2.x + f2.y) + (f3.x + f3.y);
        if (g == 0) sum += xp_cur;          // xp enters the reduction once
        sum += __shfl_xor_sync(0xffffffffu, sum, 1);
        sum += __shfl_xor_sync(0xffffffffu, sum, 2);
        sum += __shfl_xor_sync(0xffffffffu, sum, 4);

        float v = fast_tanh(sum);           // uniform across the 8-lane group
        xp_cur = xp_next;

        // lane 0 gathers the warp's 4 outputs; one local + one remote v4 store
        float v1 = __shfl_sync(0xffffffffu, v, 8);
        float v2 = __shfl_sync(0xffffffffu, v, 16);
        float v3 = __shfl_sync(0xffffffffu, v, 24);
        if (l == 0) {
            *(float4*)&hbuf[pn][ownK + w * 4] = make_float4(v, v1, v2, v3);
            st_remote_v4(rD0 + (uint32_t)(pn * HDIM * 4), v, v1, v2, v3);
        }
        __syncthreads();                    // all reads of buf[p] done; local h visible
        // re-arm buf[p] peer-half for the peer's write 2 steps from now
        // (peer's next write lands >= 1 full round-trip after our send above)
        if (tid < 128) hbuf[p][peerK + tid] = __uint_as_float(CANARY);
    }

    // classifier: rank 0 assembles full final h (poll peer half of final buf)
    if (rank == 0 && tid < 64) {
        const float* hf = hbuf[len & 1];
        int c = tid >> 5, lane = tid & 31;
        // poll this lane's 4 peer-half inputs (indices 128..255 -> m=4..7)
        uint32_t a4 = s2u(&hf[lane + 32 * 4]);
        uint32_t a5 = s2u(&hf[lane + 32 * 5]);
        uint32_t a6 = s2u(&hf[lane + 32 * 6]);
        uint32_t a7 = s2u(&hf[lane + 32 * 7]);
        uint32_t u4, u5, u6, u7;
        for (;;) {
            asm volatile("ld.volatile.shared.u32 %0, [%1];" : "=r"(u4) : "r"(a4));
            asm volatile("ld.volatile.shared.u32 %0, [%1];" : "=r"(u5) : "r"(a5));
            asm volatile("ld.volatile.shared.u32 %0, [%1];" : "=r"(u6) : "r"(a6));
            asm volatile("ld.volatile.shared.u32 %0, [%1];" : "=r"(u7) : "r"(a7));
            if ((u4 != CANARY) & (u5 != CANARY) & (u6 != CANARY) & (u7 != CANARY))
                break;
        }
        float sum = 0.0f;
#pragma unroll
        for (int m = 0; m < 4; m++)
            sum += Wcls[c * HDIM + lane + 32 * m] * hf[lane + 32 * m];
        sum += Wcls[c * HDIM + lane + 128] * __uint_as_float(u4);
        sum += Wcls[c * HDIM + lane + 160] * __uint_as_float(u5);
        sum += Wcls[c * HDIM + lane + 192] * __uint_as_float(u6);
        sum += Wcls[c * HDIM + lane + 224] * __uint_as_float(u7);
#pragma unroll
        for (int o = 16; o > 0; o >>= 1) sum += __shfl_down_sync(0xffffffffu, sum, o);
        if (lane == 0) out[b * 2 + c] = sum + bcls[c];
    }

    // keep both CTAs alive until all cross-CTA traffic has landed
    cl_arrive(); cl_wait();
}

// ---------------------------------------------------------------------------
extern "C" void kernel_launch(void* const* d_in, const int* in_sizes, int n_in,
                              void* d_out, int out_size) {
    const int*   reviews = (const int*)d_in[0];
    const int*   lengths = (const int*)d_in[1];
    const float* emb     = (const float*)d_in[2];
    const float* Wih     = (const float*)d_in[3];
    const float* Whh     = (const float*)d_in[4];
    const float* Wcls    = (const float*)d_in[5];
    const float* bcls    = (const float*)d_in[6];
    float*       out     = (float*)d_out;

    dim3 gA(2, (VOCAB + 127) / 128);
    proj_kernel<<<gA, 256>>>(emb, Wih);

    scan_kernel<<<BATCH * 2, 1024>>>(reviews, lengths, Whh, Wcls, bcls, out);
}

// round 11
// speedup vs baseline: 2.8008x; 1.7406x over previous
#include <cuda_runtime.h>
#include <cstdint>

#define VOCAB 50000
#define EDIM  256
#define HDIM  256
#define BATCH 64
#define TLEN  2048

#define CANARY 0x7FC00BADu

typedef unsigned long long u64;

// proj_table[v][h] = sum_e emb[v][e] * W_ih[h][e]   (51.2 MB device scratch)
__device__ float g_proj[VOCAB * HDIM];

// ---------------------------------------------------------------------------
// Kernel A: proj = emb @ W_ih^T   (NT SGEMM, C[50000,256])  -- unchanged
// ---------------------------------------------------------------------------
__global__ __launch_bounds__(256) void proj_kernel(const float* __restrict__ emb,
                                                   const float* __restrict__ Wih) {
    __shared__ float As[32][128];
    __shared__ float Bs[32][128];

    const int n0 = blockIdx.x * 128;
    const int m0 = blockIdx.y * 128;
    const int tid = threadIdx.x;
    const int tx = tid & 15;
    const int ty = tid >> 4;

    float acc[8][8];
#pragma unroll
    for (int a = 0; a < 8; a++)
#pragma unroll
        for (int bb = 0; bb < 8; bb++) acc[a][bb] = 0.0f;

    for (int kc = 0; kc < EDIM; kc += 32) {
#pragma unroll
        for (int q = 0; q < 4; q++) {
            int fid = tid + 256 * q;
            int row = fid >> 3;
            int col = fid & 7;
            float4 av = make_float4(0.f, 0.f, 0.f, 0.f);
            int m = m0 + row;
            if (m < VOCAB)
                av = __ldg((const float4*)(emb + (size_t)m * EDIM + kc + col * 4));
            As[col * 4 + 0][row] = av.x;
            As[col * 4 + 1][row] = av.y;
            As[col * 4 + 2][row] = av.z;
            As[col * 4 + 3][row] = av.w;
            float4 bv = __ldg((const float4*)(Wih + (size_t)(n0 + row) * EDIM + kc + col * 4));
            Bs[col * 4 + 0][row] = bv.x;
            Bs[col * 4 + 1][row] = bv.y;
            Bs[col * 4 + 2][row] = bv.z;
            Bs[col * 4 + 3][row] = bv.w;
        }
        __syncthreads();

#pragma unroll
        for (int k = 0; k < 32; k++) {
            float a[8], b[8];
            *(float4*)&a[0] = *(const float4*)&As[k][ty * 8];
            *(float4*)&a[4] = *(const float4*)&As[k][ty * 8 + 4];
            *(float4*)&b[0] = *(const float4*)&Bs[k][tx * 8];
            *(float4*)&b[4] = *(const float4*)&Bs[k][tx * 8 + 4];
#pragma unroll
            for (int ii = 0; ii < 8; ii++)
#pragma unroll
                for (int jj = 0; jj < 8; jj++) acc[ii][jj] += a[ii] * b[jj];
        }
        __syncthreads();
    }

#pragma unroll
    for (int ii = 0; ii < 8; ii++) {
        int m = m0 + ty * 8 + ii;
        if (m < VOCAB) {
            float4 v0 = make_float4(acc[ii][0], acc[ii][1], acc[ii][2], acc[ii][3]);
            float4 v1 = make_float4(acc[ii][4], acc[ii][5], acc[ii][6], acc[ii][7]);
            *(float4*)(g_proj + (size_t)m * HDIM + n0 + tx * 8)     = v0;
            *(float4*)(g_proj + (size_t)m * HDIM + n0 + tx * 8 + 4) = v1;
        }
    }
}

// ---------------------------------------------------------------------------
// Kernel B: RNN scan. 64 clusters x 2 CTAs x 1024 threads.
// R1's thin-tail skeleton (ps smem reduce, tanh in 128 threads, scalar
// remote stores, 2x __syncthreads). The in-loop cluster barrier is replaced
// by: ONE peer-half warp polls the 128 incoming floats for canary-free,
// then releases the 16 peer-half warps via bar.sync(1,512). Own-half warps
// never wait on cross-CTA data. Double-buffered h with poison recycling.
// Thread layout (R1): i = tid&127 (output), s = tid>>7 (32-K slice).
// ---------------------------------------------------------------------------
__device__ __forceinline__ void fma2(u64& acc, u64 a, u64 b) {
    asm("fma.rn.f32x2 %0, %1, %2, %0;" : "+l"(acc) : "l"(a), "l"(b));
}
__device__ __forceinline__ uint32_t s2u(const void* p) {
    return (uint32_t)__cvta_generic_to_shared(p);
}
__device__ __forceinline__ uint32_t mapa_u32(uint32_t a, uint32_t r) {
    uint32_t ret;
    asm("mapa.shared::cluster.u32 %0, %1, %2;" : "=r"(ret) : "r"(a), "r"(r));
    return ret;
}
__device__ __forceinline__ void st_remote_f32(uint32_t ra, float v) {
    asm volatile("st.shared::cluster.f32 [%0], %1;" :: "r"(ra), "f"(v) : "memory");
}
__device__ __forceinline__ uint4 ldsv4_vol(uint32_t a) {
    uint4 r;
    asm volatile("ld.volatile.shared.v4.u32 {%0, %1, %2, %3}, [%4];"
                 : "=r"(r.x), "=r"(r.y), "=r"(r.z), "=r"(r.w) : "r"(a));
    return r;
}
__device__ __forceinline__ void bar_sync_named(int bid, int cnt) {
    asm volatile("bar.sync %0, %1;" :: "r"(bid), "r"(cnt) : "memory");
}
__device__ __forceinline__ void cl_arrive() {
    asm volatile("barrier.cluster.arrive.aligned;" ::: "memory");
}
__device__ __forceinline__ void cl_wait() {
    asm volatile("barrier.cluster.wait.aligned;" ::: "memory");
}
// exact-enough tanh (validated rel_err ~2.7e-7 end-to-end, R5-R9)
__device__ __forceinline__ float fast_tanh(float x) {
    float xc = fminf(fmaxf(x, -15.0f), 15.0f);
    float e  = __expf(2.0f * xc);
    return __fdividef(e - 1.0f, e + 1.0f);
}

__global__ void __cluster_dims__(2, 1, 1) __launch_bounds__(1024, 1)
scan_kernel(const int* __restrict__ reviews, const int* __restrict__ lengths,
            const float* __restrict__ Whh, const float* __restrict__ Wcls,
            const float* __restrict__ bcls, float* __restrict__ out) {
    __shared__ __align__(16) float hbuf[2][HDIM];   // full h, double-buffered
    __shared__ float ps[8][128];                    // per-slice partials
    __shared__ int toks[TLEN];

    const int tid  = threadIdx.x;
    const int warp = tid >> 5;
    const int lane = tid & 31;
    const int i    = tid & 127;             // output index within the half
    const int s    = tid >> 7;              // K-slice 0..7 (K = s*32..s*32+31)
    const int b    = blockIdx.x >> 1;
    const int rank = blockIdx.x & 1;
    const int peer = rank ^ 1;
    const int len  = lengths[b];
    const int ownK  = rank * 128;           // h range produced locally
    const int peerK = 128 - ownK;
    const bool ownHalf  = ((s >> 2) == rank);       // slice reads local h half
    const bool isPollW  = (warp == (rank ? 0 : 31));// one peer-half warp polls

    for (int idx = tid; idx < TLEN; idx += 1024)
        toks[idx] = reviews[b * TLEN + idx];
    if (tid < HDIM) hbuf[0][tid] = 0.0f;                        // t=0 state
    if (tid < 128)  hbuf[1][peerK + tid] = __uint_as_float(CANARY);  // armed

    // W_hh[ownK + i][s*32 .. s*32+31] as 16 packed f32x2
    u64 w[16];
    {
        const u64* wp = (const u64*)(Whh + (size_t)(ownK + i) * HDIM + s * 32);
#pragma unroll
        for (int q = 0; q < 16; q++) w[q] = wp[q];
    }
    __syncthreads();
    cl_arrive(); cl_wait();                 // peer's canary init visible

    // remote h slots for the 128 writer threads (both phases)
    uint32_t rH0 = 0, rH1 = 0;
    if (tid < 128) {
        rH0 = mapa_u32(s2u(&hbuf[0][ownK + tid]), peer);
        rH1 = mapa_u32(s2u(&hbuf[1][ownK + tid]), peer);
    }
    // poll addresses: lane l watches hbuf[x][peerK + 4l .. +3]
    const uint32_t pa0 = s2u(&hbuf[0][peerK + 4 * lane]);
    const uint32_t pa1 = s2u(&hbuf[1][peerK + 4 * lane]);

    float xp_cur = 0.0f;
    if (tid < 128) xp_cur = __ldg(g_proj + (size_t)toks[0] * HDIM + ownK + tid);

    for (int t = 0; t < len; ++t) {
        const int p = t & 1, pn = p ^ 1;

        // prefetch next step's xp (writers only; hidden under FMA/wait)
        float xp_next = 0.0f;
        if (tid < 128) {
            int tn = (t + 1 < len) ? (t + 1) : t;
            xp_next = __ldg(g_proj + (size_t)toks[tn] * HDIM + ownK + tid);
        }

        if (!ownHalf) {
            // peer-half warps: one warp polls arrival, then releases the group
            if (isPollW) {
                const uint32_t pa = p ? pa1 : pa0;
                for (;;) {
                    uint4 c = ldsv4_vol(pa);
                    bool ok = (c.x != CANARY) & (c.y != CANARY) &
                              (c.z != CANARY) & (c.w != CANARY);
                    if (__all_sync(0xffffffffu, ok)) break;
                }
            }
            bar_sync_named(1, 512);         // 16 peer-half warps
        }

        // slice FMAs (own-half: guarded by prior sync#2; peer-half: by bar 1)
        u64 a0 = 0ull, a1 = 0ull;
        {
            const ulonglong2* hp = (const ulonglong2*)&hbuf[p][s * 32];
#pragma unroll
            for (int q = 0; q < 8; q++) {
                ulonglong2 hh = hp[q];      // broadcast across the warp
                fma2(a0, w[2 * q],     hh.x);
                fma2(a1, w[2 * q + 1], hh.y);
            }
        }
        float2 f0 = *(float2*)&a0, f1 = *(float2*)&a1;
        ps[s][i] = (f0.x + f0.y) + (f1.x + f1.y);
        __syncthreads();                    // sync#1: all ps ready, all reads done

        // re-arm buf[p] peer half (peer rewrites it >= 1 round-trip later)
        if (tid >= 128 && tid < 256)
            hbuf[p][peerK + (tid - 128)] = __uint_as_float(CANARY);

        if (tid < 128) {                    // thin serial tail: 4 warps
            float sum = xp_cur;
#pragma unroll
            for (int q = 0; q < 8; q++) sum += ps[q][tid];
            float v = fast_tanh(sum);
            hbuf[pn][ownK + tid] = v;               // local copy
            st_remote_f32(pn ? rH1 : rH0, v);       // peer copy (DSMEM)
            xp_cur = xp_next;
        }
        __syncthreads();                    // sync#2: local h + poison visible
    }

    // classifier: rank 0 assembles full final h (poll peer half of final buf)
    if (rank == 0 && tid < 64) {
        const float* hf = hbuf[len & 1];
        int c = tid >> 5, ln = tid & 31;
        uint32_t a4 = s2u(&hf[ln + 128]);
        uint32_t a5 = s2u(&hf[ln + 160]);
        uint32_t a6 = s2u(&hf[ln + 192]);
        uint32_t a7 = s2u(&hf[ln + 224]);
        uint32_t u4, u5, u6, u7;
        for (;;) {
            asm volatile("ld.volatile.shared.u32 %0, [%1];" : "=r"(u4) : "r"(a4));
            asm volatile("ld.volatile.shared.u32 %0, [%1];" : "=r"(u5) : "r"(a5));
            asm volatile("ld.volatile.shared.u32 %0, [%1];" : "=r"(u6) : "r"(a6));
            asm volatile("ld.volatile.shared.u32 %0, [%1];" : "=r"(u7) : "r"(a7));
            if ((u4 != CANARY) & (u5 != CANARY) & (u6 != CANARY) & (u7 != CANARY))
                break;
        }
        float sum = 0.0f;
#pragma unroll
        for (int m = 0; m < 4; m++)
            sum += Wcls[c * HDIM + ln + 32 * m] * hf[ln + 32 * m];
        sum += Wcls[c * HDIM + ln + 128] * __uint_as_float(u4);
        sum += Wcls[c * HDIM + ln + 160] * __uint_as_float(u5);
        sum += Wcls[c * HDIM + ln + 192] * __uint_as_float(u6);
        sum += Wcls[c * HDIM + ln + 224] * __uint_as_float(u7);
#pragma unroll
        for (int o = 16; o > 0; o >>= 1) sum += __shfl_down_sync(0xffffffffu, sum, o);
        if (ln == 0) out[b * 2 + c] = sum + bcls[c];
    }

    // keep both CTAs alive until all cross-CTA traffic has landed
    cl_arrive(); cl_wait();
}

// ---------------------------------------------------------------------------
extern "C" void kernel_launch(void* const* d_in, const int* in_sizes, int n_in,
                              void* d_out, int out_size) {
    const int*   reviews = (const int*)d_in[0];
    const int*   lengths = (const int*)d_in[1];
    const float* emb     = (const float*)d_in[2];
    const float* Wih     = (const float*)d_in[3];
    const float* Whh     = (const float*)d_in[4];
    const float* Wcls    = (const float*)d_in[5];
    const float* bcls    = (const float*)d_in[6];
    float*       out     = (float*)d_out;

    dim3 gA(2, (VOCAB + 127) / 128);
    proj_kernel<<<gA, 256>>>(emb, Wih);

    scan_kernel<<<BATCH * 2, 1024>>>(reviews, lengths, Whh, Wcls, bcls, out);
}

// round 12
// speedup vs baseline: 3.4966x; 1.2484x over previous
#include <cuda_runtime.h>
#include <cstdint>

#define VOCAB 50000
#define EDIM  256
#define HDIM  256
#define BATCH 64
#define TLEN  2048

#define CANARY 0x7FC00BADu

typedef unsigned long long u64;

// proj_table[v][h] = sum_e emb[v][e] * W_ih[h][e]   (51.2 MB device scratch)
__device__ float g_proj[VOCAB * HDIM];

// ---------------------------------------------------------------------------
// Kernel A: proj = emb @ W_ih^T   (NT SGEMM, C[50000,256])  -- unchanged
// ---------------------------------------------------------------------------
__global__ __launch_bounds__(256) void proj_kernel(const float* __restrict__ emb,
                                                   const float* __restrict__ Wih) {
    __shared__ float As[32][128];
    __shared__ float Bs[32][128];

    const int n0 = blockIdx.x * 128;
    const int m0 = blockIdx.y * 128;
    const int tid = threadIdx.x;
    const int tx = tid & 15;
    const int ty = tid >> 4;

    float acc[8][8];
#pragma unroll
    for (int a = 0; a < 8; a++)
#pragma unroll
        for (int bb = 0; bb < 8; bb++) acc[a][bb] = 0.0f;

    for (int kc = 0; kc < EDIM; kc += 32) {
#pragma unroll
        for (int q = 0; q < 4; q++) {
            int fid = tid + 256 * q;
            int row = fid >> 3;
            int col = fid & 7;
            float4 av = make_float4(0.f, 0.f, 0.f, 0.f);
            int m = m0 + row;
            if (m < VOCAB)
                av = __ldg((const float4*)(emb + (size_t)m * EDIM + kc + col * 4));
            As[col * 4 + 0][row] = av.x;
            As[col * 4 + 1][row] = av.y;
            As[col * 4 + 2][row] = av.z;
            As[col * 4 + 3][row] = av.w;
            float4 bv = __ldg((const float4*)(Wih + (size_t)(n0 + row) * EDIM + kc + col * 4));
            Bs[col * 4 + 0][row] = bv.x;
            Bs[col * 4 + 1][row] = bv.y;
            Bs[col * 4 + 2][row] = bv.z;
            Bs[col * 4 + 3][row] = bv.w;
        }
        __syncthreads();

#pragma unroll
        for (int k = 0; k < 32; k++) {
            float a[8], b[8];
            *(float4*)&a[0] = *(const float4*)&As[k][ty * 8];
            *(float4*)&a[4] = *(const float4*)&As[k][ty * 8 + 4];
            *(float4*)&b[0] = *(const float4*)&Bs[k][tx * 8];
            *(float4*)&b[4] = *(const float4*)&Bs[k][tx * 8 + 4];
#pragma unroll
            for (int ii = 0; ii < 8; ii++)
#pragma unroll
                for (int jj = 0; jj < 8; jj++) acc[ii][jj] += a[ii] * b[jj];
        }
        __syncthreads();
    }

#pragma unroll
    for (int ii = 0; ii < 8; ii++) {
        int m = m0 + ty * 8 + ii;
        if (m < VOCAB) {
            float4 v0 = make_float4(acc[ii][0], acc[ii][1], acc[ii][2], acc[ii][3]);
            float4 v1 = make_float4(acc[ii][4], acc[ii][5], acc[ii][6], acc[ii][7]);
            *(float4*)(g_proj + (size_t)m * HDIM + n0 + tx * 8)     = v0;
            *(float4*)(g_proj + (size_t)m * HDIM + n0 + tx * 8 + 4) = v1;
        }
    }
}

// ---------------------------------------------------------------------------
// Kernel B: RNN scan. 64 clusters x 2 CTAs x 1024 threads.
// R10 skeleton (canary-poll DSMEM exchange, thin tail) + split-phase reduce:
//   slice remap ks=(s+4*rank)&7 makes warps 0-15 own-half / 16-31 peer-half
//   in BOTH CTAs. Tail = warps 0-3. bar1: poll release (warps 16-31).
//   bar2: own-half ps -> tail. bar3: peer-half ps -> tail. bar5: peer group
//   internal (before poison). One __syncthreads at step end.
// ---------------------------------------------------------------------------
__device__ __forceinline__ void fma2(u64& acc, u64 a, u64 b) {
    asm("fma.rn.f32x2 %0, %1, %2, %0;" : "+l"(acc) : "l"(a), "l"(b));
}
__device__ __forceinline__ uint32_t s2u(const void* p) {
    return (uint32_t)__cvta_generic_to_shared(p);
}
__device__ __forceinline__ uint32_t mapa_u32(uint32_t a, uint32_t r) {
    uint32_t ret;
    asm("mapa.shared::cluster.u32 %0, %1, %2;" : "=r"(ret) : "r"(a), "r"(r));
    return ret;
}
__device__ __forceinline__ void st_remote_f32(uint32_t ra, float v) {
    asm volatile("st.shared::cluster.f32 [%0], %1;" :: "r"(ra), "f"(v) : "memory");
}
__device__ __forceinline__ uint4 ldsv4_vol(uint32_t a) {
    uint4 r;
    asm volatile("ld.volatile.shared.v4.u32 {%0, %1, %2, %3}, [%4];"
                 : "=r"(r.x), "=r"(r.y), "=r"(r.z), "=r"(r.w) : "r"(a));
    return r;
}
__device__ __forceinline__ void bar_sync_named(int bid, int cnt) {
    asm volatile("bar.sync %0, %1;" :: "r"(bid), "r"(cnt) : "memory");
}
__device__ __forceinline__ void bar_arrive_named(int bid, int cnt) {
    asm volatile("bar.arrive %0, %1;" :: "r"(bid), "r"(cnt) : "memory");
}
__device__ __forceinline__ void cl_arrive() {
    asm volatile("barrier.cluster.arrive.aligned;" ::: "memory");
}
__device__ __forceinline__ void cl_wait() {
    asm volatile("barrier.cluster.wait.aligned;" ::: "memory");
}
// exact-enough tanh (validated rel_err ~2.9e-7 end-to-end, R5-R10)
__device__ __forceinline__ float fast_tanh(float x) {
    float xc = fminf(fmaxf(x, -15.0f), 15.0f);
    float e  = __expf(2.0f * xc);
    return __fdividef(e - 1.0f, e + 1.0f);
}

__global__ void __cluster_dims__(2, 1, 1) __launch_bounds__(1024, 1)
scan_kernel(const int* __restrict__ reviews, const int* __restrict__ lengths,
            const float* __restrict__ Whh, const float* __restrict__ Wcls,
            const float* __restrict__ bcls, float* __restrict__ out) {
    __shared__ __align__(16) float hbuf[2][HDIM];   // full h, double-buffered
    __shared__ float ps[8][128];                    // per-slice partials
    __shared__ int toks[TLEN];

    const int tid  = threadIdx.x;
    const int warp = tid >> 5;
    const int lane = tid & 31;
    const int i    = tid & 127;             // output index within the half
    const int s    = tid >> 7;              // slice group 0..7
    const int b    = blockIdx.x >> 1;
    const int rank = blockIdx.x & 1;
    const int peer = rank ^ 1;
    const int len  = lengths[b];
    const int ownK  = rank * 128;           // h range produced locally
    const int peerK = 128 - ownK;
    const int ks    = (s + 4 * rank) & 7;   // K block handled: warps 0-15 own,
                                            // warps 16-31 peer (both ranks)
    for (int idx = tid; idx < TLEN; idx += 1024)
        toks[idx] = reviews[b * TLEN + idx];
    if (tid < HDIM) hbuf[0][tid] = 0.0f;                        // t=0 state
    if (tid < 128)  hbuf[1][peerK + tid] = __uint_as_float(CANARY);  // armed

    // W_hh[ownK + i][ks*32 .. ks*32+31] as 16 packed f32x2
    u64 w[16];
    {
        const u64* wp = (const u64*)(Whh + (size_t)(ownK + i) * HDIM + ks * 32);
#pragma unroll
        for (int q = 0; q < 16; q++) w[q] = wp[q];
    }
    __syncthreads();
    cl_arrive(); cl_wait();                 // peer's canary init visible

    // remote h slots for the tail threads (both phases)
    uint32_t rH0 = 0, rH1 = 0;
    if (tid < 128) {
        rH0 = mapa_u32(s2u(&hbuf[0][ownK + tid]), peer);
        rH1 = mapa_u32(s2u(&hbuf[1][ownK + tid]), peer);
    }
    // poll addresses (warp 16): lane l watches hbuf[x][peerK + 4l .. +3]
    const uint32_t pa0 = s2u(&hbuf[0][peerK + 4 * lane]);
    const uint32_t pa1 = s2u(&hbuf[1][peerK + 4 * lane]);

    float xp_cur = 0.0f;
    if (tid < 128) xp_cur = __ldg(g_proj + (size_t)toks[0] * HDIM + ownK + tid);

    for (int t = 0; t < len; ++t) {
        const int p = t & 1, pn = p ^ 1;

        if (warp < 4) {
            // ---------------- tail warps (own slice ks, + serial tail) ------
            int tn = (t + 1 < len) ? (t + 1) : t;
            float xp_next = __ldg(g_proj + (size_t)toks[tn] * HDIM + ownK + tid);

            u64 a0 = 0ull, a1 = 0ull;
            const ulonglong2* hp = (const ulonglong2*)&hbuf[p][ks * 32];
#pragma unroll
            for (int q = 0; q < 8; q++) {
                ulonglong2 hh = hp[q];
                fma2(a0, w[2 * q],     hh.x);
                fma2(a1, w[2 * q + 1], hh.y);
            }
            float2 f0 = *(float2*)&a0, f1 = *(float2*)&a1;
            float own0 = (f0.x + f0.y) + (f1.x + f1.y);

            bar_sync_named(2, 512);         // own-half ps (warps 4-15) ready
            float sum = xp_cur + own0 + ps[1][i] + ps[2][i] + ps[3][i];
            bar_sync_named(3, 640);         // peer-half ps (warps 16-31) ready
            sum += ps[4][i] + ps[5][i] + ps[6][i] + ps[7][i];
            float v = fast_tanh(sum);
            st_remote_f32(pn ? rH1 : rH0, v);   // long-latency first
            hbuf[pn][ownK + tid] = v;           // local copy
            xp_cur = xp_next;
        } else if (warp < 16) {
            // ---------------- own-half producer warps -----------------------
            u64 a0 = 0ull, a1 = 0ull;
            const ulonglong2* hp = (const ulonglong2*)&hbuf[p][ks * 32];
#pragma unroll
            for (int q = 0; q < 8; q++) {
                ulonglong2 hh = hp[q];
                fma2(a0, w[2 * q],     hh.x);
                fma2(a1, w[2 * q + 1], hh.y);
            }
            float2 f0 = *(float2*)&a0, f1 = *(float2*)&a1;
            ps[s][i] = (f0.x + f0.y) + (f1.x + f1.y);
            bar_arrive_named(2, 512);
        } else {
            // ---------------- peer-half warps (poll-gated) ------------------
            if (warp == 16) {               // single poll warp
                const uint32_t pa = p ? pa1 : pa0;
                for (;;) {
                    uint4 c = ldsv4_vol(pa);
                    bool ok = (c.x != CANARY) & (c.y != CANARY) &
                              (c.z != CANARY) & (c.w != CANARY);
                    if (__all_sync(0xffffffffu, ok)) break;
                }
            }
            bar_sync_named(1, 512);         // release 16 peer-half warps

            u64 a0 = 0ull, a1 = 0ull;
            const ulonglong2* hp = (const ulonglong2*)&hbuf[p][ks * 32];
#pragma unroll
            for (int q = 0; q < 8; q++) {
                ulonglong2 hh = hp[q];
                fma2(a0, w[2 * q],     hh.x);
                fma2(a1, w[2 * q + 1], hh.y);
            }
            float2 f0 = *(float2*)&a0, f1 = *(float2*)&a1;
            ps[s][i] = (f0.x + f0.y) + (f1.x + f1.y);
            bar_arrive_named(3, 640);

            bar_sync_named(5, 512);         // all peer-half reads of buf[p] done
            if (tid < 640)                  // 128 threads re-arm buf[p] peer half
                hbuf[p][peerK + (tid - 512)] = __uint_as_float(CANARY);
        }
        __syncthreads();                    // step closure: local h visible
    }

    // classifier: rank 0 assembles full final h (poll peer half of final buf)
    if (rank == 0 && tid < 64) {
        const float* hf = hbuf[len & 1];
        int c = tid >> 5, ln = tid & 31;
        uint32_t a4 = s2u(&hf[ln + 128]);
        uint32_t a5 = s2u(&hf[ln + 160]);
        uint32_t a6 = s2u(&hf[ln + 192]);
        uint32_t a7 = s2u(&hf[ln + 224]);
        uint32_t u4, u5, u6, u7;
        for (;;) {
            asm volatile("ld.volatile.shared.u32 %0, [%1];" : "=r"(u4) : "r"(a4));
            asm volatile("ld.volatile.shared.u32 %0, [%1];" : "=r"(u5) : "r"(a5));
            asm volatile("ld.volatile.shared.u32 %0, [%1];" : "=r"(u6) : "r"(a6));
            asm volatile("ld.volatile.shared.u32 %0, [%1];" : "=r"(u7) : "r"(a7));
            if ((u4 != CANARY) & (u5 != CANARY) & (u6 != CANARY) & (u7 != CANARY))
                break;
        }
        float sum = 0.0f;
#pragma unroll
        for (int m = 0; m < 4; m++)
            sum += Wcls[c * HDIM + ln + 32 * m] * hf[ln + 32 * m];
        sum += Wcls[c * HDIM + ln + 128] * __uint_as_float(u4);
        sum += Wcls[c * HDIM + ln + 160] * __uint_as_float(u5);
        sum += Wcls[c * HDIM + ln + 192] * __uint_as_float(u6);
        sum += Wcls[c * HDIM + ln + 224] * __uint_as_float(u7);
#pragma unroll
        for (int o = 16; o > 0; o >>= 1) sum += __shfl_down_sync(0xffffffffu, sum, o);
        if (ln == 0) out[b * 2 + c] = sum + bcls[c];
    }

    // keep both CTAs alive until all cross-CTA traffic has landed
    cl_arrive(); cl_wait();
}

// ---------------------------------------------------------------------------
extern "C" void kernel_launch(void* const* d_in, const int* in_sizes, int n_in,
                              void* d_out, int out_size) {
    const int*   reviews = (const int*)d_in[0];
    const int*   lengths = (const int*)d_in[1];
    const float* emb     = (const float*)d_in[2];
    const float* Wih     = (const float*)d_in[3];
    const float* Whh     = (const float*)d_in[4];
    const float* Wcls    = (const float*)d_in[5];
    const float* bcls    = (const float*)d_in[6];
    float*       out     = (float*)d_out;

    dim3 gA(2, (VOCAB + 127) / 128);
    proj_kernel<<<gA, 256>>>(emb, Wih);

    scan_kernel<<<BATCH * 2, 1024>>>(reviews, lengths, Whh, Wcls, bcls, out);
}